// round 3
// baseline (speedup 1.0000x reference)
#include <cuda_runtime.h>
#include <cuda_bf16.h>

// ---------------- problem constants ----------------
#define H_IMG   2048
#define W_IMG   2048
#define C_IMG   3
#define RAD     5
#define NITER   10
#define PH      (H_IMG + 2*RAD)   // 2058
#define PW      (W_IMG + 2*RAD)   // 2058

// Guarded buffer layout: interior pixel (y,x) (y in [0,PH), x in [0,PW))
// lives at row y+GY, col x+GX. Guard bands are kept zero so the iteration
// kernel can load float4 tiles with NO bounds checks.
#define GY      8                 // top guard rows
#define GX      8                 // left guard cols
#define PROWS   2104              // 8 top + 2058 + 38 bottom guard rows
#define PITCH   2208              // 8 left + 2058 + 142 right guard cols (x4B, 128B aligned)
#define PLANE   (PROWS * PITCH)   // floats per channel plane
#define BUFSZ   (C_IMG * PLANE)   // floats per ping-pong buffer

__device__ float g_U[2][BUFSZ];

// ---------------- zero all guard bands of both buffers ----------------
// Regions per plane: top rows [0,8), bottom rows [2066,2104),
// left cols [0,8) rows [8,2066), right cols [2066,2208) rows [8,2066).
#define NA (8 * PITCH)
#define NB (38 * PITCH)
#define NL (PH * 8)
#define NR (PH * 142)
#define NGUARD (NA + NB + NL + NR)

__global__ void swf_guard_zero() {
    int plane = blockIdx.y;            // 0..5 : b*3 + c
    int b = plane / 3;
    int c = plane - b * 3;
    float* base = g_U[b] + c * PLANE;
    for (int i = blockIdx.x * blockDim.x + threadIdx.x; i < NGUARD;
         i += gridDim.x * blockDim.x) {
        int row, col, r = i;
        if (r < NA)                { row = r / PITCH;            col = r % PITCH; }
        else if ((r -= NA) < NB)   { row = 2066 + r / PITCH;     col = r % PITCH; }
        else if ((r -= NB) < NL)   { row = GY + r / 8;           col = r % 8; }
        else        { r -= NL;       row = GY + r / 142;          col = 2066 + r % 142; }
        base[row * PITCH + col] = 0.0f;
    }
}

// ---------------- pad (edge replicate) HWC -> planar padded interior ----------------
__global__ void swf_pad(const float* __restrict__ img) {
    int total = C_IMG * PH * PW;
    for (int i = blockIdx.x * blockDim.x + threadIdx.x; i < total;
         i += gridDim.x * blockDim.x) {
        int x = i % PW;
        int t = i / PW;
        int y = t % PH;
        int c = t / PH;
        int sy = y - RAD; sy = sy < 0 ? 0 : (sy > H_IMG - 1 ? H_IMG - 1 : sy);
        int sx = x - RAD; sx = sx < 0 ? 0 : (sx > W_IMG - 1 ? W_IMG - 1 : sx);
        g_U[0][c * PLANE + (y + GY) * PITCH + (x + GX)] =
            img[(sy * W_IMG + sx) * C_IMG + c];
    }
}

// ---------------- one side-window iteration ----------------
#define TH 32
#define TW 128
#define TROWS (TH + 2*RAD)        // 42
#define TCOLS 144                 // 36 float4: covers gx in [x0-8, x0+136)
#define TC4   (TCOLS/4)           // 36
#define NF4   (TROWS * TC4)       // 1512 float4 tile loads
#define H6W   136                 // >= 133 used, padded stride

__global__ __launch_bounds__(256)
void swf_iter(int s) {
    const float* __restrict__ S = g_U[s];
    float* __restrict__ D = g_U[s ^ 1];

    __shared__ float tile[TROWS * TCOLS];   // 42*144 = 6048 floats
    __shared__ float h6[TROWS * H6W];       // 42*136 = 5712 floats

    const int c  = blockIdx.z;
    const int x0 = blockIdx.x * TW;
    const int y0 = blockIdx.y * TH;
    const int t  = threadIdx.x;             // 0..255
    const float* __restrict__ Sp = S + c * PLANE;
    float* __restrict__ Dp = D + c * PLANE;

    // ---- Stage 1: unconditional float4 tile load (guards supply zeros) ----
    // tile col 0 <-> buffer col x0 (i.e. gx = x0-8); tile row r <-> buffer row y0+3+r.
    {
        const float4* __restrict__ Sp4 =
            (const float4*)(Sp + (y0 + 3) * PITCH + x0);
        float4* tile4 = (float4*)tile;
        #pragma unroll
        for (int k = 0; k < 6; k++) {
            int idx = t + k * 256;
            if (idx < NF4) {
                int r  = idx / TC4;
                int c4 = idx - r * TC4;
                tile4[r * TC4 + c4] = Sp4[r * (PITCH / 4) + c4];
            }
        }
    }
    __syncthreads();

    // ---- Stage 2: horizontal extended 6-sums, sliding windows ----
    // h6[r][cc] = sum tile[r][cc+3 .. cc+8]  (covers gx window x0-5+cc .. x0+cc)
    if (t < 252) {
        int r   = t % 42;
        int seg = t / 42;                // 0..5
        int sx  = seg * 23;
        int ex  = sx + 23; if (ex > 133) ex = 133;
        const float* trow = &tile[r * TCOLS];
        float* hrow = &h6[r * H6W];
        float sum = trow[sx + 3] + trow[sx + 4] + trow[sx + 5]
                  + trow[sx + 6] + trow[sx + 7] + trow[sx + 8];
        hrow[sx] = sum;
        for (int cc = sx + 1; cc < ex; cc++) {
            sum += trow[cc + 8] - trow[cc + 2];
            hrow[cc] = sum;
        }
    }
    __syncthreads();

    // ---- Stage 3: per-thread vertical walk with register ring buffers ----
    const int lx   = t & 127;
    const int half = t >> 7;
    const int base = half * (TH / 2);
    const int gx   = x0 + lx;
    const bool xok = (gx < PW);

    const float i36 = 1.0f / 36.0f;
    const float i66 = 1.0f / 66.0f;

    float rHL[12], rHR[12], rC[12];
    #pragma unroll
    for (int i = 0; i < 11; i++) {
        int row = base + i;
        rHL[i] = h6[row * H6W + lx];
        rHR[i] = h6[row * H6W + lx + 5];
        rC[i]  = tile[row * TCOLS + lx + 8];
    }

    float uL = 0.f, uR = 0.f, Vu = 0.f, dL = 0.f, dR = 0.f, Vd = 0.f;
    #pragma unroll
    for (int i = 0; i < 6; i++)  { uL += rHL[i]; uR += rHR[i]; Vu += rC[i]; }
    #pragma unroll
    for (int i = 5; i < 11; i++) { dL += rHL[i]; dR += rHR[i]; Vd += rC[i]; }

    float* Drow = Dp + (y0 + base + GY) * PITCH + gx + GX;

    #pragma unroll
    for (int ly = 0; ly < TH / 2; ly++) {
        if (ly > 0) {
            const int slot = (10 + ly) % 12;
            const int row  = base + 10 + ly;
            float nHL = h6[row * H6W + lx];
            float nHR = h6[row * H6W + lx + 5];
            float nC  = tile[row * TCOLS + lx + 8];
            const int du = (ly - 1) % 12;
            const int au = (5 + ly) % 12;
            const int dd = (4 + ly) % 12;
            uL += rHL[au] - rHL[du];
            uR += rHR[au] - rHR[du];
            Vu += rC[au]  - rC[du];
            dL += nHL - rHL[dd];
            dR += nHR - rHR[dd];
            Vd += nC  - rC[dd];
            rHL[slot] = nHL; rHR[slot] = nHR; rC[slot] = nC;
        }

        const int cs = (5 + ly) % 12;
        const float c0  = rC[cs];
        const float nc0 = -c0;
        const float hL = rHL[cs];
        const float hR = rHR[cs];

        const float uF = uL + uR - Vu;
        const float dF = dL + dR - Vd;
        const float fL = uL + dL - hL;
        const float fR = uR + dR - hR;

        // deltas, reference order [LL,LR,RL,RR,L*k,R*k,k*L,k*R]
        const float d0 = fmaf(uL, i36, nc0);
        const float d1 = fmaf(uR, i36, nc0);
        const float d2 = fmaf(dL, i36, nc0);
        const float d3 = fmaf(dR, i36, nc0);
        const float d4 = fmaf(uF, i66, nc0);
        const float d5 = fmaf(dF, i66, nc0);
        const float d6 = fmaf(fL, i66, nc0);
        const float d7 = fmaf(fR, i66, nc0);

        // first-min argmin: strict < against running min, FMNMX + FSETP + FSEL
        float bd = d0;
        float ba = fabsf(d0);
        bd = (fabsf(d1) < ba) ? d1 : bd;  ba = fminf(fabsf(d1), ba);
        bd = (fabsf(d2) < ba) ? d2 : bd;  ba = fminf(fabsf(d2), ba);
        bd = (fabsf(d3) < ba) ? d3 : bd;  ba = fminf(fabsf(d3), ba);
        bd = (fabsf(d4) < ba) ? d4 : bd;  ba = fminf(fabsf(d4), ba);
        bd = (fabsf(d5) < ba) ? d5 : bd;  ba = fminf(fabsf(d5), ba);
        bd = (fabsf(d6) < ba) ? d6 : bd;  ba = fminf(fabsf(d6), ba);
        bd = (fabsf(d7) < ba) ? d7 : bd;

        const int gy = y0 + base + ly;
        if (xok && gy < PH) {
            Drow[ly * PITCH] = c0 + bd;
        }
    }
}

// ---------------- crop planar padded -> HWC output ----------------
__global__ void swf_crop(float* __restrict__ out) {
    int total = H_IMG * W_IMG * C_IMG;
    for (int i = blockIdx.x * blockDim.x + threadIdx.x; i < total;
         i += gridDim.x * blockDim.x) {
        int c = i % C_IMG;
        int t = i / C_IMG;
        int x = t % W_IMG;
        int y = t / W_IMG;
        out[i] = g_U[0][c * PLANE + (y + RAD + GY) * PITCH + (x + RAD + GX)];
    }
}

extern "C" void kernel_launch(void* const* d_in, const int* in_sizes, int n_in,
                              void* d_out, int out_size) {
    const float* img = (const float*)d_in[0];   // (2048,2048,3) f32; d_in[1] hardcoded
    float* out = (float*)d_out;

    {
        dim3 grid(512, 6, 1);
        swf_guard_zero<<<grid, 256>>>();
    }
    {
        int total = C_IMG * PH * PW;
        int threads = 256;
        int blocks = (total + threads - 1) / threads;
        if (blocks > 65535) blocks = 65535;
        swf_pad<<<blocks, threads>>>(img);
    }

    dim3 block(256, 1, 1);
    dim3 grid((PW + TW - 1) / TW, (PH + TH - 1) / TH, C_IMG);
    for (int i = 0; i < NITER; i++) {
        swf_iter<<<grid, block>>>(i & 1);
    }

    {
        int total = H_IMG * W_IMG * C_IMG;
        int threads = 256;
        int blocks = (total + threads - 1) / threads;
        if (blocks > 65535) blocks = 65535;
        swf_crop<<<blocks, threads>>>(out);
    }
}

// round 4
// speedup vs baseline: 1.7607x; 1.7607x over previous
#include <cuda_runtime.h>
#include <cuda_bf16.h>

// ---------------- problem constants ----------------
#define H_IMG   2048
#define W_IMG   2048
#define C_IMG   3
#define RAD     5
#define NITER   10
#define PH      (H_IMG + 2*RAD)   // 2058
#define PW      (W_IMG + 2*RAD)   // 2058

// Guarded buffer layout: interior pixel (y,x) lives at row y+GY, col x+GX.
// Guard bands stay zero so the iteration kernel loads float4 with NO bounds checks.
#define GY      8
#define GX      8
#define PROWS   2104              // 8 top + 2058 + 38 bottom guard rows
#define PITCH   2208              // 8 left + 2058 + 142 right guard cols
#define PLANE   (PROWS * PITCH)
#define BUFSZ   (C_IMG * PLANE)

__device__ float g_U[2][BUFSZ];

// ---------------- zero all guard bands of both buffers ----------------
#define NA (8 * PITCH)
#define NB (38 * PITCH)
#define NL (PH * 8)
#define NR (PH * 142)
#define NGUARD (NA + NB + NL + NR)

__global__ void swf_guard_zero() {
    int plane = blockIdx.y;            // 0..5 : b*3 + c
    int b = plane / 3;
    int c = plane - b * 3;
    float* base = g_U[b] + c * PLANE;
    for (int i = blockIdx.x * blockDim.x + threadIdx.x; i < NGUARD;
         i += gridDim.x * blockDim.x) {
        int row, col, r = i;
        if (r < NA)                { row = r / PITCH;            col = r % PITCH; }
        else if ((r -= NA) < NB)   { row = 2066 + r / PITCH;     col = r % PITCH; }
        else if ((r -= NB) < NL)   { row = GY + r / 8;           col = r % 8; }
        else        { r -= NL;       row = GY + r / 142;          col = 2066 + r % 142; }
        base[row * PITCH + col] = 0.0f;
    }
}

// ---------------- pad (edge replicate) HWC -> planar padded interior ----------------
__global__ void swf_pad(const float* __restrict__ img) {
    int total = C_IMG * PH * PW;
    for (int i = blockIdx.x * blockDim.x + threadIdx.x; i < total;
         i += gridDim.x * blockDim.x) {
        int x = i % PW;
        int t = i / PW;
        int y = t % PH;
        int c = t / PH;
        int sy = y - RAD; sy = sy < 0 ? 0 : (sy > H_IMG - 1 ? H_IMG - 1 : sy);
        int sx = x - RAD; sx = sx < 0 ? 0 : (sx > W_IMG - 1 ? W_IMG - 1 : sx);
        g_U[0][c * PLANE + (y + GY) * PITCH + (x + GX)] =
            img[(sy * W_IMG + sx) * C_IMG + c];
    }
}

// ---------------- one side-window iteration ----------------
#define TH 32
#define TW 128
#define TROWS (TH + 2*RAD)        // 42
#define TCOLS 148                 // 37 float4; bank-friendly stride (20 mod 32)
#define TC4   (TCOLS/4)           // 37
#define NF4   (TROWS * TC4)       // 1554 float4 tile loads
#define H6W   136                 // >= 133 used

__global__ __launch_bounds__(256)
void swf_iter(int s) {
    const float* __restrict__ S = g_U[s];
    float* __restrict__ D = g_U[s ^ 1];

    __shared__ float tile[TROWS * TCOLS];   // 42*148 = 6216 floats
    __shared__ float h6[TROWS * H6W];       // 42*136 = 5712 floats

    const int c  = blockIdx.z;
    const int x0 = blockIdx.x * TW;
    const int y0 = blockIdx.y * TH;
    const int t  = threadIdx.x;             // 0..255
    const float* __restrict__ Sp = S + c * PLANE;
    float* __restrict__ Dp = D + c * PLANE;

    // ---- Stage 1: unconditional float4 tile load (guards supply zeros) ----
    // tile col 0 <-> buffer col x0 (gx = x0-8); tile row r <-> buffer row y0+3+r.
    {
        const float4* __restrict__ Sp4 =
            (const float4*)(Sp + (y0 + 3) * PITCH + x0);
        float4* tile4 = (float4*)tile;
        #pragma unroll
        for (int k = 0; k < 7; k++) {
            int idx = t + k * 256;
            if (idx < NF4) {
                int r  = idx / TC4;
                int c4 = idx - r * TC4;
                tile4[r * TC4 + c4] = Sp4[r * (PITCH / 4) + c4];
            }
        }
    }
    __syncthreads();

    // ---- Stage 2: horizontal extended 6-sums, per-thread sliding windows ----
    // h6[r][cc] = sum tile[r][cc+3 .. cc+8]   (gx window x0-5+cc .. x0+cc)
    // mapping r = t/6 keeps lanes mostly within a row-group: <=2-way conflicts.
    if (t < 252) {
        int r   = t / 6;
        int seg = t - r * 6;                 // 0..5
        int sx  = seg * 23;
        int ex  = sx + 23; if (ex > 133) ex = 133;
        const float* trow = &tile[r * TCOLS];
        float* hrow = &h6[r * H6W];
        float sum = trow[sx + 3] + trow[sx + 4] + trow[sx + 5]
                  + trow[sx + 6] + trow[sx + 7] + trow[sx + 8];
        hrow[sx] = sum;
        for (int cc = sx + 1; cc < ex; cc++) {
            sum += trow[cc + 8] - trow[cc + 2];
            hrow[cc] = sum;
        }
    }
    __syncthreads();

    // ---- Stage 3: per-thread vertical walk with register ring buffers ----
    const int lx   = t & 127;
    const int half = t >> 7;
    const int base = half * (TH / 2);
    const int gx   = x0 + lx;
    const bool xok = (gx < PW);

    const float i36 = 1.0f / 36.0f;
    const float i66 = 1.0f / 66.0f;

    float rHL[12], rHR[12], rC[12];
    #pragma unroll
    for (int i = 0; i < 11; i++) {
        int row = base + i;
        rHL[i] = h6[row * H6W + lx];
        rHR[i] = h6[row * H6W + lx + 5];
        rC[i]  = tile[row * TCOLS + lx + 8];
    }

    float uL = 0.f, uR = 0.f, Vu = 0.f, dL = 0.f, dR = 0.f, Vd = 0.f;
    #pragma unroll
    for (int i = 0; i < 6; i++)  { uL += rHL[i]; uR += rHR[i]; Vu += rC[i]; }
    #pragma unroll
    for (int i = 5; i < 11; i++) { dL += rHL[i]; dR += rHR[i]; Vd += rC[i]; }

    float* Drow = Dp + (y0 + base + GY) * PITCH + gx + GX;

    #pragma unroll
    for (int ly = 0; ly < TH / 2; ly++) {
        if (ly > 0) {
            const int slot = (10 + ly) % 12;
            const int row  = base + 10 + ly;
            float nHL = h6[row * H6W + lx];
            float nHR = h6[row * H6W + lx + 5];
            float nC  = tile[row * TCOLS + lx + 8];
            const int du = (ly - 1) % 12;
            const int au = (5 + ly) % 12;
            const int dd = (4 + ly) % 12;
            uL += rHL[au] - rHL[du];
            uR += rHR[au] - rHR[du];
            Vu += rC[au]  - rC[du];
            dL += nHL - rHL[dd];
            dR += nHR - rHR[dd];
            Vd += nC  - rC[dd];
            rHL[slot] = nHL; rHR[slot] = nHR; rC[slot] = nC;
        }

        const int cs = (5 + ly) % 12;
        const float c0  = rC[cs];
        const float nc0 = -c0;
        const float hL = rHL[cs];
        const float hR = rHR[cs];

        const float uF = uL + uR - Vu;
        const float dF = dL + dR - Vd;
        const float fL = uL + dL - hL;
        const float fR = uR + dR - hR;

        // deltas, reference order [LL,LR,RL,RR,L*k,R*k,k*L,k*R]
        const float d0 = fmaf(uL, i36, nc0);
        const float d1 = fmaf(uR, i36, nc0);
        const float d2 = fmaf(dL, i36, nc0);
        const float d3 = fmaf(dR, i36, nc0);
        const float d4 = fmaf(uF, i66, nc0);
        const float d5 = fmaf(dF, i66, nc0);
        const float d6 = fmaf(fL, i66, nc0);
        const float d7 = fmaf(fR, i66, nc0);

        // Tournament argmin, first-min-on-tie (strict < picks the later element
        // only when strictly smaller; left group indices < right group indices).
        float w01 = (fabsf(d1) < fabsf(d0)) ? d1 : d0;
        float a01 = fminf(fabsf(d1), fabsf(d0));
        float w23 = (fabsf(d3) < fabsf(d2)) ? d3 : d2;
        float a23 = fminf(fabsf(d3), fabsf(d2));
        float w45 = (fabsf(d5) < fabsf(d4)) ? d5 : d4;
        float a45 = fminf(fabsf(d5), fabsf(d4));
        float w67 = (fabsf(d7) < fabsf(d6)) ? d7 : d6;
        float a67 = fminf(fabsf(d7), fabsf(d6));

        float w03 = (a23 < a01) ? w23 : w01;
        float a03 = fminf(a23, a01);
        float w47 = (a67 < a45) ? w67 : w45;
        float a47 = fminf(a67, a45);

        float bd = (a47 < a03) ? w47 : w03;

        const int gy = y0 + base + ly;
        if (xok && gy < PH) {
            Drow[ly * PITCH] = c0 + bd;
        }
    }
}

// ---------------- crop planar padded -> HWC output ----------------
__global__ void swf_crop(float* __restrict__ out) {
    int total = H_IMG * W_IMG * C_IMG;
    for (int i = blockIdx.x * blockDim.x + threadIdx.x; i < total;
         i += gridDim.x * blockDim.x) {
        int c = i % C_IMG;
        int t = i / C_IMG;
        int x = t % W_IMG;
        int y = t / W_IMG;
        out[i] = g_U[0][c * PLANE + (y + RAD + GY) * PITCH + (x + RAD + GX)];
    }
}

extern "C" void kernel_launch(void* const* d_in, const int* in_sizes, int n_in,
                              void* d_out, int out_size) {
    const float* img = (const float*)d_in[0];   // (2048,2048,3) f32; d_in[1] hardcoded
    float* out = (float*)d_out;

    {
        dim3 grid(512, 6, 1);
        swf_guard_zero<<<grid, 256>>>();
    }
    {
        int total = C_IMG * PH * PW;
        int threads = 256;
        int blocks = (total + threads - 1) / threads;
        if (blocks > 65535) blocks = 65535;
        swf_pad<<<blocks, threads>>>(img);
    }

    dim3 block(256, 1, 1);
    dim3 grid((PW + TW - 1) / TW, (PH + TH - 1) / TH, C_IMG);
    for (int i = 0; i < NITER; i++) {
        swf_iter<<<grid, block>>>(i & 1);
    }

    {
        int total = H_IMG * W_IMG * C_IMG;
        int threads = 256;
        int blocks = (total + threads - 1) / threads;
        if (blocks > 65535) blocks = 65535;
        swf_crop<<<blocks, threads>>>(out);
    }
}